// round 15
// baseline (speedup 1.0000x reference)
#include <cuda_runtime.h>
#include <math.h>

#define N_ENT 50000
#define N_REL 237
#define N_TYPE 4000
#define DE 100
#define NOUT 128
#define DT 200
#define DTP 224
#define N_EDGE 800000
#define BATCH 4096
#define NUM_FILT 32
#define CONV_W 60
#define POOL_W 30
#define FC_LEN 960
#define EPS 1e-5f

#define SAP 36
#define ES_PITCH 132   // 528 bytes: 16B-aligned row pitch for cp.async
#define OUT_SMEM (2 * (128 + 256) * SAP * 4)
// k_fc: A 2*64*SAP + B 2*256*SAP (unsigned) + es 64*ES_PITCH + w3 288 + b3 32 (float)
#define FC_SMEM ((2 * 64 * SAP + 2 * 256 * SAP) * 4 + (64 * ES_PITCH + 288 + 32) * 4)

// ---------------- scratch ----------------
__device__ float g_hm[N_ENT];
__device__ float g_wa1[DE];
__device__ float g_wa2[DE];
__device__ float g_ra[N_REL];
__device__ int   g_flag[N_ENT];
__device__ float g_hdc[BATCH];
__device__ float g_denomc[BATCH];
__device__ float g_Cagg[BATCH * DE];
__device__ int   g_ecnt;
__device__ int   g_cs[N_EDGE];
__device__ int   g_cdp[N_EDGE];
__device__ int   g_ct[N_EDGE];
__device__ float g_ex[N_EDGE];
__device__ float g_e[BATCH * NOUT];
__device__ float g_y[BATCH * DT];
__device__ float g_z[BATCH * DTP];
__device__ float g_twc[N_TYPE * DTP];
__device__ float g_fcwc[DT * FC_LEN];
__device__ float g_bn1[4];
__device__ float g_T[9];
__device__ float g_M[45];
__device__ float g_w3[NUM_FILT * 9];
__device__ float g_b3[NUM_FILT];
__device__ float g_bn2sum[DT], g_bn2ss[DT];
__device__ float g_bn2sc[DT], g_bn2sh[DT];
__device__ unsigned g_c1, g_c2, g_c4;

// ---------------- helpers ----------------
__device__ __forceinline__ unsigned f2tf(float x) {
    unsigned r;
    asm("cvt.rna.tf32.f32 %0, %1;" : "=r"(r) : "f"(x));
    return r;
}

__device__ __forceinline__ void mma_tf32(float c[4], const unsigned a[4], const unsigned b[2]) {
    asm volatile(
        "mma.sync.aligned.m16n8k8.row.col.f32.tf32.tf32.f32 "
        "{%0,%1,%2,%3}, {%4,%5,%6,%7}, {%8,%9}, {%0,%1,%2,%3};"
        : "+f"(c[0]), "+f"(c[1]), "+f"(c[2]), "+f"(c[3])
        : "r"(a[0]), "r"(a[1]), "r"(a[2]), "r"(a[3]), "r"(b[0]), "r"(b[1]));
}

__device__ __forceinline__ void cp16(unsigned dst, const void* src) {
    asm volatile("cp.async.ca.shared.global [%0], [%1], 16;" :: "r"(dst), "l"(src));
}
__device__ __forceinline__ void cp_commit() { asm volatile("cp.async.commit_group;"); }
__device__ __forceinline__ void cp_wait1() { asm volatile("cp.async.wait_group 1;" ::: "memory"); }
__device__ __forceinline__ void cp_wait0() { asm volatile("cp.async.wait_group 0;" ::: "memory"); }

// 64x64 warp tile inner loop (k_out)
__device__ __forceinline__ void gemm_compute(const unsigned* __restrict__ A,
                                             const unsigned* __restrict__ B,
                                             float c[4][8][4], int wm, int wn,
                                             int g, int tg) {
#pragma unroll
    for (int kk = 0; kk < 4; kk++) {
        int k0 = kk * 8;
        unsigned ar[4][4];
#pragma unroll
        for (int mt = 0; mt < 4; mt++) {
            int rb = (wm * 64 + mt * 16 + g) * SAP + k0 + tg;
            ar[mt][0] = A[rb];
            ar[mt][1] = A[rb + 8 * SAP];
            ar[mt][2] = A[rb + 4];
            ar[mt][3] = A[rb + 8 * SAP + 4];
        }
#pragma unroll
        for (int nt = 0; nt < 8; nt++) {
            int nb = (wn * 64 + nt * 8 + g) * SAP + k0 + tg;
            unsigned br[2] = {B[nb], B[nb + 4]};
#pragma unroll
            for (int mt = 0; mt < 4; mt++) mma_tf32(c[mt][nt], ar[mt], br);
        }
    }
}

// 32x64 warp tile inner loop (k_fc)
__device__ __forceinline__ void gemm_fc(const unsigned* __restrict__ A,
                                        const unsigned* __restrict__ B,
                                        float c[2][8][4], int wm, int wn,
                                        int g, int tg) {
#pragma unroll
    for (int kk = 0; kk < 4; kk++) {
        int k0 = kk * 8;
        unsigned ar[2][4];
#pragma unroll
        for (int mt = 0; mt < 2; mt++) {
            int rb = (wm * 32 + mt * 16 + g) * SAP + k0 + tg;
            ar[mt][0] = A[rb];
            ar[mt][1] = A[rb + 8 * SAP];
            ar[mt][2] = A[rb + 4];
            ar[mt][3] = A[rb + 8 * SAP + 4];
        }
#pragma unroll
        for (int nt = 0; nt < 8; nt++) {
            int nb = (wn * 64 + nt * 8 + g) * SAP + k0 + tg;
            unsigned br[2] = {B[nb], B[nb + 4]};
#pragma unroll
            for (int mt = 0; mt < 2; mt++) mma_tf32(c[mt][nt], ar[mt], br);
        }
    }
}

// ---------------- small kernels ----------------

// fused: wa vectors + all zero-init
__global__ void k_init(const float* __restrict__ Wf, const float* __restrict__ av) {
    int b = blockIdx.x, t = threadIdx.x;
    if (b < 13) {
        int k = b * 8 + (t >> 5);
        int lane = t & 31;
        if (k < DE) {
            float s1 = 0.f, s2 = 0.f;
#pragma unroll
            for (int q = 0; q < 4; q++) {
                int j = lane + q * 32;
                float w = Wf[k * NOUT + j];
                s1 += w * av[j];
                s2 += w * av[NOUT + j];
            }
#pragma unroll
            for (int o = 16; o > 0; o >>= 1) {
                s1 += __shfl_xor_sync(0xffffffffu, s1, o);
                s2 += __shfl_xor_sync(0xffffffffu, s2, o);
            }
            if (lane == 0) { g_wa1[k] = s1; g_wa2[k] = s2; }
        }
    }
    int tid = b * blockDim.x + t;
    int stride = gridDim.x * blockDim.x;
    for (int i = tid; i < N_ENT; i += stride) g_flag[i] = 0;
    if (tid == 0) { g_ecnt = 0; g_c1 = 0u; g_c2 = 0u; g_c4 = 0u; }
    if (tid < 2) g_bn1[tid] = 0.f;
    if (tid < 9) g_T[tid] = 0.f;
    if (tid < 45) g_M[tid] = 0.f;
    if (tid < DT) { g_bn2sum[tid] = 0.f; g_bn2ss[tid] = 0.f; }
}

// flag dst nodes (value b+1), zero Cagg row + denom, compute hd for the row
__global__ void k_flag(const int* __restrict__ xb, const float* __restrict__ Ew) {
    int b = blockIdx.x, t = threadIdx.x;
    int n = xb[b];
    if (t == 0) g_flag[n] = b + 1;
    if (t >= 32 && t - 32 < DE) g_Cagg[b * DE + (t - 32)] = 0.f;
    if (t == 32 + DE) g_denomc[b] = 0.f;
    if (t < 32) {
        float s = 0.f;
        for (int k = t; k < DE; k += 32) s += Ew[n * DE + k] * g_wa1[k];
#pragma unroll
        for (int o = 16; o > 0; o >>= 1) s += __shfl_xor_sync(0xffffffffu, s, o);
        if (t == 0) g_hdc[b] = s;
    }
}

// hm[n] = Ew[n].wa2 ; ra[r] = Rw[r].wa2  (thread per row, 25 float4 MLP)
__global__ void k_hmra(const float* __restrict__ Ew, const float* __restrict__ Rw) {
    __shared__ float wa[DE];
    int t = threadIdx.x;
    if (t < DE) wa[t] = g_wa2[t];
    __syncthreads();
    int idx = blockIdx.x * 256 + t;
    const float* row;
    if (idx < N_ENT) row = Ew + (size_t)idx * DE;
    else if (idx < N_ENT + N_REL) row = Rw + (size_t)(idx - N_ENT) * DE;
    else return;
    const float4* r4 = reinterpret_cast<const float4*>(row);
    float s = 0.f;
#pragma unroll
    for (int q = 0; q < DE / 4; q++) {
        float4 v = __ldg(r4 + q);
        s += v.x * wa[4 * q] + v.y * wa[4 * q + 1] + v.z * wa[4 * q + 2] + v.w * wa[4 * q + 3];
    }
    if (idx < N_ENT) g_hm[idx] = s;
    else g_ra[idx - N_ENT] = s;
}

// compact edges whose dst is flagged + fused score/exp/denom
__global__ void k_compact(const int* __restrict__ ei, const int* __restrict__ et) {
    int e = blockIdx.x * blockDim.x + threadIdx.x;
    int lane = threadIdx.x & 31;
    int f = 0;
    bool pred = false;
    if (e < N_EDGE) {
        f = g_flag[ei[N_EDGE + e]];
        pred = (f != 0);
    }
    unsigned mask = __ballot_sync(0xffffffffu, pred);
    if (mask == 0) return;
    int leader = __ffs(mask) - 1;
    int base = 0;
    if (lane == leader) base = atomicAdd(&g_ecnt, __popc(mask));
    base = __shfl_sync(0xffffffffu, base, leader);
    if (pred) {
        int pos = base + __popc(mask & ((1u << lane) - 1u));
        int src = ei[e], t = et[e], p = f - 1;
        g_cs[pos] = src;
        g_cdp[pos] = p;
        g_ct[pos] = t;
        float s = g_hdc[p] + g_hm[src] - g_ra[t];
        s = (s >= 0.f) ? s : 0.2f * s;
        float ex = expf(s);
        g_ex[pos] = ex;
        atomicAdd(&g_denomc[p], ex);
    }
}

__global__ void k_agg(const float* __restrict__ Ew, const float* __restrict__ Rw) {
    int w = (blockIdx.x * blockDim.x + threadIdx.x) >> 5;
    int nwarp = (gridDim.x * blockDim.x) >> 5;
    int lane = threadIdx.x & 31;
    int cnt = g_ecnt;
    for (int e = w; e < cnt; e += nwarp) {
        int src = g_cs[e], p = g_cdp[e], t = g_ct[e];
        float wt = g_ex[e] / (g_denomc[p] + 1e-16f);
        if (lane < DE / 4) {
            float4 a = reinterpret_cast<const float4*>(&Ew[src * DE])[lane];
            float4 b = reinterpret_cast<const float4*>(&Rw[t * DE])[lane];
            float4 v;
            v.x = wt * (a.x - b.x); v.y = wt * (a.y - b.y);
            v.z = wt * (a.z - b.z); v.w = wt * (a.w - b.w);
            float* pp = &g_Cagg[p * DE + lane * 4];
            asm volatile("red.global.add.v4.f32 [%0], {%1,%2,%3,%4};"
                         :: "l"(pp), "f"(v.x), "f"(v.y), "f"(v.z), "f"(v.w) : "memory");
        }
    }
}

// gather Cagg rows, project through Wf, elu, bn1 stats (+ last-block finalize)
__global__ void k_gatherproj(const int* __restrict__ xb, const float* __restrict__ Wf,
                             const float* __restrict__ b1g, const float* __restrict__ b1b) {
    int b0 = blockIdx.x * 16;
    int t = threadIdx.x;
    __shared__ float C[16][DE];
    __shared__ int posr[16];
    __shared__ float r1[128], r2[128];
    if (t < 16) posr[t] = g_flag[xb[b0 + t]] - 1;
    __syncthreads();
    for (int i = t; i < 16 * DE; i += 128) {
        int r = i / DE, k = i % DE;
        C[r][k] = g_Cagg[posr[r] * DE + k];
    }
    __syncthreads();
    int jl = t & 31, ng = t >> 5;
    float acc[4][4];
#pragma unroll
    for (int a = 0; a < 4; a++)
#pragma unroll
        for (int b = 0; b < 4; b++) acc[a][b] = 0.f;
    for (int k = 0; k < DE; k++) {
        float w0 = Wf[k * NOUT + jl];
        float w1 = Wf[k * NOUT + jl + 32];
        float w2 = Wf[k * NOUT + jl + 64];
        float w3 = Wf[k * NOUT + jl + 96];
#pragma unroll
        for (int nn = 0; nn < 4; nn++) {
            float e = C[ng * 4 + nn][k];
            acc[nn][0] += e * w0;
            acc[nn][1] += e * w1;
            acc[nn][2] += e * w2;
            acc[nn][3] += e * w3;
        }
    }
    float s = 0.f, ss = 0.f;
#pragma unroll
    for (int nn = 0; nn < 4; nn++)
#pragma unroll
        for (int q = 0; q < 4; q++) {
            float v = acc[nn][q];
            float e = (v > 0.f) ? v : expm1f(v);
            g_e[(b0 + ng * 4 + nn) * NOUT + q * 32 + jl] = e;
            s += e; ss += e * e;
        }
    r1[t] = s; r2[t] = ss;
    __syncthreads();
    for (int o = 64; o > 0; o >>= 1) {
        if (t < o) { r1[t] += r1[t + o]; r2[t] += r2[t + o]; }
        __syncthreads();
    }
    if (t == 0) { atomicAdd(&g_bn1[0], r1[0]); atomicAdd(&g_bn1[1], r2[0]); }
    __threadfence();
    __shared__ int lastf;
    if (t == 0) lastf = (atomicAdd(&g_c1, 1u) == gridDim.x - 1) ? 1 : 0;
    __syncthreads();
    if (lastf && t == 0) {
        float cnt = (float)(BATCH * NOUT);
        float mean = g_bn1[0] / cnt;
        float var = g_bn1[1] / cnt - mean * mean;
        float inv = rsqrtf(var + EPS);
        float sc = b1g[0] * inv;
        g_bn1[2] = sc;
        g_bn1[3] = b1b[0] - sc * mean;
    }
}

// analytic bn3 stats: T[9], M[45] over g_e, then last block computes folded
// conv weights w3/b3 (bn1 + conv + cb + bn3 all folded).
__global__ void k_stats(const float* __restrict__ cw, const float* __restrict__ cb,
                        const float* __restrict__ b3g, const float* __restrict__ b3b) {
    __shared__ float rows[32][129];
    int t = threadIdx.x;
    int r0 = blockIdx.x * 32;
    for (int i = t; i < 32 * 32; i += 256) {
        int r = i >> 5, c4 = i & 31;
        float4 v = reinterpret_cast<const float4*>(&g_e[(r0 + r) * NOUT])[c4];
        rows[r][c4 * 4 + 0] = v.x; rows[r][c4 * 4 + 1] = v.y;
        rows[r][c4 * 4 + 2] = v.z; rows[r][c4 * 4 + 3] = v.w;
    }
    __syncthreads();
    int warp = t >> 5, lane = t & 31;
    float T[9], M[45];
#pragma unroll
    for (int k = 0; k < 9; k++) T[k] = 0.f;
#pragma unroll
    for (int k = 0; k < 45; k++) M[k] = 0.f;
#pragma unroll
    for (int rr = 0; rr < 4; rr++) {
        int r = warp * 4 + rr;
#pragma unroll
        for (int jj = 0; jj < 2; jj++) {
            int j = lane + jj * 32;
            if (j < CONV_W) {
                float win[9];
#pragma unroll
                for (int k = 0; k < 9; k++) win[k] = rows[r][2 * j + k];
                int idx = 0;
#pragma unroll
                for (int k = 0; k < 9; k++) {
                    T[k] += win[k];
#pragma unroll
                    for (int k2 = k; k2 < 9; k2++) M[idx++] += win[k] * win[k2];
                }
            }
        }
    }
#pragma unroll
    for (int k = 0; k < 9; k++) {
        float v = T[k];
#pragma unroll
        for (int o = 16; o > 0; o >>= 1) v += __shfl_xor_sync(0xffffffffu, v, o);
        if (lane == 0) atomicAdd(&g_T[k], v);
    }
#pragma unroll
    for (int k = 0; k < 45; k++) {
        float v = M[k];
#pragma unroll
        for (int o = 16; o > 0; o >>= 1) v += __shfl_xor_sync(0xffffffffu, v, o);
        if (lane == 0) atomicAdd(&g_M[k], v);
    }
    __threadfence();
    __shared__ int lastf;
    if (t == 0) lastf = (atomicAdd(&g_c4, 1u) == gridDim.x - 1) ? 1 : 0;
    __syncthreads();
    if (lastf && t < NUM_FILT) {
        int c = t;
        float sc1 = g_bn1[2], sh1 = g_bn1[3];
        float W1[9], wsum = 0.f;
#pragma unroll
        for (int k = 0; k < 9; k++) {
            float w = cw[c * 9 + k];
            W1[k] = sc1 * w;
            wsum += w;
        }
        float B2 = cb[c] + sh1 * wsum;
        float St = 0.f;
#pragma unroll
        for (int k = 0; k < 9; k++) St += W1[k] * g_T[k];
        float Sq = 0.f;
        int idx = 0;
#pragma unroll
        for (int k = 0; k < 9; k++)
#pragma unroll
            for (int k2 = k; k2 < 9; k2++) {
                float m = g_M[idx++];
                Sq += ((k == k2) ? 1.f : 2.f) * W1[k] * W1[k2] * m;
            }
        const float N = (float)(BATCH * CONV_W);
        float mean = B2 + St / N;
        float E2 = B2 * B2 + 2.f * B2 * St / N + Sq / N;
        float var = E2 - mean * mean;
        float inv = rsqrtf(var + EPS);
        float sc3 = b3g[c] * inv;
        float sh3 = b3b[c] - sc3 * mean;
#pragma unroll
        for (int k = 0; k < 9; k++) g_w3[c * 9 + k] = sc3 * W1[k];
        g_b3[c] = sc3 * B2 + sh3;
    }
}

// prep: tf32 weight copies + zero g_y (split-K accumulator)
#define P1 (DT * FC_LEN)
#define P2 (N_TYPE * DTP)
#define P3 (BATCH * DT)
__global__ void k_prep(const float* __restrict__ fcw, const float* __restrict__ Tw) {
    int i = blockIdx.x * blockDim.x + threadIdx.x;
    if (i < P1) {
        g_fcwc[i] = __uint_as_float(f2tf(fcw[i]));
    } else if (i < P1 + P2) {
        int j = i - P1;
        int n = j / DTP, k = j % DTP;
        float v = (k < DT) ? Tw[n * DT + k] : 0.f;
        g_twc[j] = __uint_as_float(f2tf(v));
    } else if (i < P1 + P2 + P3) {
        g_y[i - P1 - P2] = 0.f;
    }
}

// ---------------- tf32 GEMM 1: fc (split-K, fused conv+bn3+relu+pool A) ----------------
#define FC_BM 64
__global__ void __launch_bounds__(256) k_fc() {
    extern __shared__ unsigned sm[];
    unsigned* As = sm;                           // [2][64*SAP]
    unsigned* Bs = sm + 2 * 64 * SAP;            // [2][256*SAP]
    float* es = (float*)(sm + 2 * 64 * SAP + 2 * 256 * SAP);  // [64][ES_PITCH]
    float* w3s = es + 64 * ES_PITCH;             // [32*9]
    float* b3s = w3s + 288;                      // [32]
    int t = threadIdx.x;
    int warp = t >> 5, lane = t & 31;
    int wm = warp >> 2, wn = warp & 3;           // 2x4 warps, tile 32x64
    int g = lane >> 2, tg = lane & 3;
    int m0 = blockIdx.x * FC_BM;
    int kbase = blockIdx.y * 256;
    int nch = (blockIdx.y < 3) ? 8 : 6;          // 960 = 256*3 + 192

    // stage es rows (raw g_e) via cp.async — ES_PITCH keeps dst 16B-aligned
    for (int i = t; i < 64 * 32; i += 256) {
        int r = i >> 5, c = i & 31;
        unsigned d = (unsigned)__cvta_generic_to_shared(&es[r * ES_PITCH + c * 4]);
        cp16(d, g_e + (size_t)(m0 + r) * NOUT + c * 4);
    }
    cp_commit();
    // folded conv weights
    for (int i = t; i < 288; i += 256) w3s[i] = g_w3[i];
    if (t < NUM_FILT) b3s[t] = g_b3[t];
    // zero invalid B rows (n >= 200), both buffers
    for (int i = t; i < (256 - DT) * SAP; i += 256) {
        int r = DT + i / SAP, c = i % SAP;
        Bs[r * SAP + c] = 0u;
        Bs[256 * SAP + r * SAP + c] = 0u;
    }
    cp_wait0();
    __syncthreads();

    float c[2][8][4];
#pragma unroll
    for (int i = 0; i < 2; i++)
#pragma unroll
        for (int j = 0; j < 8; j++)
#pragma unroll
            for (int q = 0; q < 4; q++) c[i][j][q] = 0.f;

    int arow = t >> 2, aq0 = (t & 3) * 8;

    auto stage = [&](int kt, int buf) {
        int k0g = kbase + kt * 32;
        // A: conv + bn3 + relu + maxpool computed from es
        unsigned* d = As + buf * 64 * SAP + arow * SAP;
        const float* er = &es[arow * ES_PITCH];
#pragma unroll
        for (int q = 0; q < 8; q++) {
            int kk = k0g + aq0 + q;
            int ch = kk / POOL_W, w = kk - ch * POOL_W;
            const float* wr = &w3s[ch * 9];
            const float* ew = er + 4 * w;
            float c0 = b3s[ch], c1 = c0;
#pragma unroll
            for (int k = 0; k < 9; k++) {
                float wv = wr[k];
                c0 += wv * ew[k];
                c1 += wv * ew[k + 2];
            }
            d[aq0 + q] = f2tf(fmaxf(fmaxf(c0, c1), 0.f));
        }
        // B: fcw rows via cp.async
        if (t < DT) {
            const float* src = g_fcwc + (size_t)t * FC_LEN + k0g;
            unsigned db = (unsigned)__cvta_generic_to_shared(Bs + buf * 256 * SAP + t * SAP);
#pragma unroll
            for (int q = 0; q < 8; q++) cp16(db + q * 16, src + q * 4);
        }
    };

    stage(0, 0);
    cp_commit();
    for (int kt = 0; kt < nch; kt++) {
        if (kt + 1 < nch) stage(kt + 1, (kt + 1) & 1);
        cp_commit();
        cp_wait1();
        __syncthreads();
        gemm_fc(As + (kt & 1) * 64 * SAP, Bs + (kt & 1) * 256 * SAP, c, wm, wn, g, tg);
        __syncthreads();
    }

#pragma unroll
    for (int mt = 0; mt < 2; mt++) {
        int mr = m0 + wm * 32 + mt * 16 + g;
#pragma unroll
        for (int nt = 0; nt < 8; nt++) {
            int n = wn * 64 + nt * 8 + 2 * tg;
            if (n < DT) {
                atomicAdd(&g_y[mr * DT + n], c[mt][nt][0]);
                atomicAdd(&g_y[mr * DT + n + 1], c[mt][nt][1]);
                atomicAdd(&g_y[(mr + 8) * DT + n], c[mt][nt][2]);
                atomicAdd(&g_y[(mr + 8) * DT + n + 1], c[mt][nt][3]);
            }
        }
    }
}

// y += bias (in place), bn2 stats, last-block finalize sc/sh
__global__ void k_ystat(const float* __restrict__ fcb, const float* __restrict__ b2g,
                        const float* __restrict__ b2b) {
    int r0 = blockIdx.x * 16, t = threadIdx.x;
    if (t < DT) {
        float bias = fcb[t];
        float s = 0.f, ss = 0.f;
#pragma unroll
        for (int i = 0; i < 16; i++) {
            float v = g_y[(r0 + i) * DT + t] + bias;
            g_y[(r0 + i) * DT + t] = v;
            s += v; ss += v * v;
        }
        atomicAdd(&g_bn2sum[t], s);
        atomicAdd(&g_bn2ss[t], ss);
    }
    __threadfence();
    __shared__ int lastf;
    if (t == 0) lastf = (atomicAdd(&g_c2, 1u) == gridDim.x - 1) ? 1 : 0;
    __syncthreads();
    if (lastf && t < DT) {
        float cnt = (float)BATCH;
        float mean = g_bn2sum[t] / cnt;
        float var = g_bn2ss[t] / cnt - mean * mean;
        float inv = rsqrtf(var + EPS);
        float sc = b2g[t] * inv;
        g_bn2sc[t] = sc;
        g_bn2sh[t] = b2b[t] - sc * mean;
    }
}

// z = relu(bn2(y)), tf32-rounded, K-padded
__global__ void k_apply() {
    int i = blockIdx.x * blockDim.x + threadIdx.x;
    if (i >= BATCH * DTP) return;
    int row = i / DTP, k = i - row * DTP;
    float v = 0.f;
    if (k < DT) {
        v = fmaxf(g_bn2sc[k] * g_y[row * DT + k] + g_bn2sh[k], 0.f);
        v = __uint_as_float(f2tf(v));
    }
    g_z[i] = v;
}

// ---------------- tf32 GEMM 2: out = sigmoid(Z @ Tw^T + bias) ----------------
__global__ void __launch_bounds__(256) k_out(const float* __restrict__ bbias,
                                             float* __restrict__ out) {
    extern __shared__ unsigned sm[];
    unsigned* As = sm;
    unsigned* Bs = sm + 2 * 128 * SAP;
    int t = threadIdx.x;
    int warp = t >> 5, lane = t & 31;
    int wm = warp >> 2, wn = warp & 3;
    int g = lane >> 2, tg = lane & 3;
    int m0 = blockIdx.x * 128;
    int n0 = blockIdx.y * 256;

    int inv0 = N_TYPE - n0;
    if (inv0 < 256) {
        for (int i = t; i < (256 - inv0) * SAP; i += 256) {
            int r = inv0 + i / SAP, c = i % SAP;
            Bs[r * SAP + c] = 0u;
            Bs[256 * SAP + r * SAP + c] = 0u;
        }
    }
    __syncthreads();

    float c[4][8][4];
#pragma unroll
    for (int i = 0; i < 4; i++)
#pragma unroll
        for (int j = 0; j < 8; j++)
#pragma unroll
            for (int q = 0; q < 4; q++) c[i][j][q] = 0.f;

    int arow = t >> 1, ahalf = (t & 1) * 16;
    const float* asrc0 = g_z + (size_t)(m0 + arow) * DTP + ahalf;
    unsigned da0 = (unsigned)__cvta_generic_to_shared(As + arow * SAP + ahalf);
    bool bvalid = (n0 + t < N_TYPE);
    const float* bsrc0 = g_twc + (size_t)(n0 + t) * DTP;
    unsigned db0 = (unsigned)__cvta_generic_to_shared(Bs + t * SAP);

    auto stage = [&](int kt, int buf) {
        int k0g = kt * 32;
        unsigned da = da0 + buf * 128 * SAP * 4;
        const float* sa = asrc0 + k0g;
#pragma unroll
        for (int q = 0; q < 4; q++) cp16(da + q * 16, sa + q * 4);
        if (bvalid) {
            unsigned db = db0 + buf * 256 * SAP * 4;
            const float* sb = bsrc0 + k0g;
#pragma unroll
            for (int q = 0; q < 8; q++) cp16(db + q * 16, sb + q * 4);
        }
    };

    const int NK = DTP / 32;
    stage(0, 0);
    cp_commit();
    for (int kt = 0; kt < NK; kt++) {
        if (kt + 1 < NK) stage(kt + 1, (kt + 1) & 1);
        cp_commit();
        cp_wait1();
        __syncthreads();
        gemm_compute(As + (kt & 1) * 128 * SAP, Bs + (kt & 1) * 256 * SAP, c, wm, wn, g, tg);
        __syncthreads();
    }

#pragma unroll
    for (int mt = 0; mt < 4; mt++) {
        int mr = m0 + wm * 64 + mt * 16 + g;
#pragma unroll
        for (int nt = 0; nt < 8; nt++) {
            int n = n0 + wn * 64 + nt * 8 + 2 * tg;
            if (n < N_TYPE) {
                float b0 = bbias[n], b1 = bbias[n + 1];
                float2 o0, o1;
                o0.x = 1.f / (1.f + expf(-(c[mt][nt][0] + b0)));
                o0.y = 1.f / (1.f + expf(-(c[mt][nt][1] + b1)));
                o1.x = 1.f / (1.f + expf(-(c[mt][nt][2] + b0)));
                o1.y = 1.f / (1.f + expf(-(c[mt][nt][3] + b1)));
                *reinterpret_cast<float2*>(&out[(size_t)mr * N_TYPE + n]) = o0;
                *reinterpret_cast<float2*>(&out[(size_t)(mr + 8) * N_TYPE + n]) = o1;
            }
        }
    }
}

// ---------------- launch ----------------
extern "C" void kernel_launch(void* const* d_in, const int* in_sizes, int n_in,
                              void* d_out, int out_size) {
    const int* xb = (const int*)d_in[0];
    const int* ei = (const int*)d_in[1];
    const int* et = (const int*)d_in[2];
    const float* Ew = (const float*)d_in[3];
    const float* Rw = (const float*)d_in[4];
    const float* Tw = (const float*)d_in[5];
    const float* Wf = (const float*)d_in[6];
    const float* av = (const float*)d_in[7];
    const float* cw = (const float*)d_in[8];
    const float* cb = (const float*)d_in[9];
    const float* b1g = (const float*)d_in[10];
    const float* b1b = (const float*)d_in[11];
    const float* b3g = (const float*)d_in[12];
    const float* b3b = (const float*)d_in[13];
    const float* b2g = (const float*)d_in[14];
    const float* b2b = (const float*)d_in[15];
    const float* fcw = (const float*)d_in[16];
    const float* fcb = (const float*)d_in[17];
    const float* bbias = (const float*)d_in[18];
    float* out = (float*)d_out;

    cudaFuncSetAttribute(k_fc, cudaFuncAttributeMaxDynamicSharedMemorySize, FC_SMEM);
    cudaFuncSetAttribute(k_out, cudaFuncAttributeMaxDynamicSharedMemorySize, OUT_SMEM);

    k_prep<<<(P1 + P2 + P3 + 255) / 256, 256>>>(fcw, Tw);
    k_init<<<256, 256>>>(Wf, av);
    k_flag<<<BATCH, 160>>>(xb, Ew);
    k_hmra<<<(N_ENT + N_REL + 255) / 256, 256>>>(Ew, Rw);
    k_compact<<<(N_EDGE + 255) / 256, 256>>>(ei, et);
    k_agg<<<1024, 256>>>(Ew, Rw);
    k_gatherproj<<<BATCH / 16, 128>>>(xb, Wf, b1g, b1b);
    k_stats<<<BATCH / 32, 256>>>(cw, cb, b3g, b3b);
    {
        dim3 gg(BATCH / FC_BM, 4);   // split-K = 4
        k_fc<<<gg, 256, FC_SMEM>>>();
    }
    k_ystat<<<BATCH / 16, 256>>>(fcb, b2g, b2b);
    k_apply<<<(BATCH * DTP + 255) / 256, 256>>>();
    {
        dim3 gg(BATCH / 128, (N_TYPE + 255) / 256);
        k_out<<<gg, 256, OUT_SMEM>>>(bbias, out);
    }
}

// round 16
// speedup vs baseline: 1.1366x; 1.1366x over previous
#include <cuda_runtime.h>
#include <math.h>

#define N_ENT 50000
#define N_REL 237
#define N_TYPE 4000
#define DE 100
#define NOUT 128
#define DT 200
#define DTP 224
#define N_EDGE 800000
#define BATCH 4096
#define NUM_FILT 32
#define CONV_W 60
#define POOL_W 30
#define FC_LEN 960
#define EPS 1e-5f

#define SAP 36
#define OUT_SMEM (2 * (128 + 256) * SAP * 4)

// ---------------- scratch ----------------
__device__ float g_hm[N_ENT];
__device__ float g_wa1[DE];
__device__ float g_wa2[DE];
__device__ float g_ra[N_REL];
__device__ int   g_flag[N_ENT];
__device__ float g_hdc[BATCH];
__device__ float g_denomc[BATCH];
__device__ float g_Cagg[BATCH * DE];
__device__ float g_e[BATCH * NOUT];
__device__ float g_conv[BATCH * NUM_FILT * CONV_W];
__device__ float g_y[BATCH * DT];
__device__ float g_z[BATCH * DTP];
__device__ float g_twc[N_TYPE * DTP];
__device__ float g_fcwc[DT * FC_LEN];
__device__ float g_bn1[4];
__device__ float g_bn3sum[NUM_FILT], g_bn3ss[NUM_FILT];
__device__ float g_bn3sc[NUM_FILT], g_bn3sh[NUM_FILT];
__device__ float g_bn2sum[DT], g_bn2ss[DT];
__device__ float g_bn2sc[DT], g_bn2sh[DT];
__device__ unsigned g_c1, g_c2, g_c3;

// ---------------- helpers ----------------
__device__ __forceinline__ unsigned f2tf(float x) {
    unsigned r;
    asm("cvt.rna.tf32.f32 %0, %1;" : "=r"(r) : "f"(x));
    return r;
}

__device__ __forceinline__ void mma_tf32(float c[4], const unsigned a[4], const unsigned b[2]) {
    asm volatile(
        "mma.sync.aligned.m16n8k8.row.col.f32.tf32.tf32.f32 "
        "{%0,%1,%2,%3}, {%4,%5,%6,%7}, {%8,%9}, {%0,%1,%2,%3};"
        : "+f"(c[0]), "+f"(c[1]), "+f"(c[2]), "+f"(c[3])
        : "r"(a[0]), "r"(a[1]), "r"(a[2]), "r"(a[3]), "r"(b[0]), "r"(b[1]));
}

__device__ __forceinline__ void cp16(unsigned dst, const void* src) {
    asm volatile("cp.async.ca.shared.global [%0], [%1], 16;" :: "r"(dst), "l"(src));
}
__device__ __forceinline__ void cp_commit() { asm volatile("cp.async.commit_group;"); }
__device__ __forceinline__ void cp_wait1() { asm volatile("cp.async.wait_group 1;" ::: "memory"); }

// 64x64 warp tile inner loop
__device__ __forceinline__ void gemm_compute(const unsigned* __restrict__ A,
                                             const unsigned* __restrict__ B,
                                             float c[4][8][4], int wm, int wn,
                                             int g, int tg) {
#pragma unroll
    for (int kk = 0; kk < 4; kk++) {
        int k0 = kk * 8;
        unsigned ar[4][4];
#pragma unroll
        for (int mt = 0; mt < 4; mt++) {
            int rb = (wm * 64 + mt * 16 + g) * SAP + k0 + tg;
            ar[mt][0] = A[rb];
            ar[mt][1] = A[rb + 8 * SAP];
            ar[mt][2] = A[rb + 4];
            ar[mt][3] = A[rb + 8 * SAP + 4];
        }
#pragma unroll
        for (int nt = 0; nt < 8; nt++) {
            int nb = (wn * 64 + nt * 8 + g) * SAP + k0 + tg;
            unsigned br[2] = {B[nb], B[nb + 4]};
#pragma unroll
            for (int mt = 0; mt < 4; mt++) mma_tf32(c[mt][nt], ar[mt], br);
        }
    }
}

// ---------------- fused prep + init ----------------
#define P1 (DT * FC_LEN)
#define P2 (N_TYPE * DTP)
#define P3 (BATCH * DT)
__global__ void k_prepinit(const float* __restrict__ Wf, const float* __restrict__ av,
                           const float* __restrict__ fcw, const float* __restrict__ Tw) {
    int b = blockIdx.x, t = threadIdx.x;
    // wa vectors (blocks 0..12)
    if (b < 13) {
        int k = b * 8 + (t >> 5);
        int lane = t & 31;
        if (k < DE) {
            float s1 = 0.f, s2 = 0.f;
#pragma unroll
            for (int q = 0; q < 4; q++) {
                int j = lane + q * 32;
                float w = Wf[k * NOUT + j];
                s1 += w * av[j];
                s2 += w * av[NOUT + j];
            }
#pragma unroll
            for (int o = 16; o > 0; o >>= 1) {
                s1 += __shfl_xor_sync(0xffffffffu, s1, o);
                s2 += __shfl_xor_sync(0xffffffffu, s2, o);
            }
            if (lane == 0) { g_wa1[k] = s1; g_wa2[k] = s2; }
        }
    }
    int i = b * blockDim.x + t;
    // tf32 weight copies + zero g_y
    if (i < P1) {
        g_fcwc[i] = __uint_as_float(f2tf(fcw[i]));
    } else if (i < P1 + P2) {
        int j = i - P1;
        int n = j / DTP, k = j % DTP;
        float v = (k < DT) ? Tw[n * DT + k] : 0.f;
        g_twc[j] = __uint_as_float(f2tf(v));
    } else if (i < P1 + P2 + P3) {
        g_y[i - P1 - P2] = 0.f;
    }
    // flags + counters + stat accumulators
    if (i < N_ENT) g_flag[i] = 0;
    if (i == 0) { g_c1 = 0u; g_c2 = 0u; g_c3 = 0u; }
    if (i < 2) g_bn1[i] = 0.f;
    if (i < NUM_FILT) { g_bn3sum[i] = 0.f; g_bn3ss[i] = 0.f; }
    if (i < DT) { g_bn2sum[i] = 0.f; g_bn2ss[i] = 0.f; }
}

// flag dst nodes (value b+1), zero Cagg row + denom, compute hd for the row
__global__ void k_flag(const int* __restrict__ xb, const float* __restrict__ Ew) {
    int b = blockIdx.x, t = threadIdx.x;
    int n = xb[b];
    if (t == 0) g_flag[n] = b + 1;
    if (t >= 32 && t - 32 < DE) g_Cagg[b * DE + (t - 32)] = 0.f;
    if (t == 32 + DE) g_denomc[b] = 0.f;
    if (t < 32) {
        float s = 0.f;
        for (int k = t; k < DE; k += 32) s += Ew[n * DE + k] * g_wa1[k];
#pragma unroll
        for (int o = 16; o > 0; o >>= 1) s += __shfl_xor_sync(0xffffffffu, s, o);
        if (t == 0) g_hdc[b] = s;
    }
}

// hm[n] = Ew[n].wa2 ; ra[r] = Rw[r].wa2  (2 threads per row: 13/12 float4 each)
__global__ void k_hmra(const float* __restrict__ Ew, const float* __restrict__ Rw) {
    __shared__ float wa[DE];
    int t = threadIdx.x;
    if (t < DE) wa[t] = g_wa2[t];
    __syncthreads();
    int gid = blockIdx.x * 256 + t;
    int idx = gid >> 1, half = gid & 1;
    if (idx >= N_ENT + N_REL) return;
    const float* row = (idx < N_ENT) ? Ew + (size_t)idx * DE
                                     : Rw + (size_t)(idx - N_ENT) * DE;
    const float4* r4 = reinterpret_cast<const float4*>(row);
    int base = half ? 13 : 0;
    int cnt = half ? 12 : 13;
    float s = 0.f;
#pragma unroll
    for (int q = 0; q < 13; q++) {
        if (q < cnt) {
            float4 v = __ldg(r4 + base + q);
            int k = (base + q) * 4;
            s += v.x * wa[k] + v.y * wa[k + 1] + v.z * wa[k + 2] + v.w * wa[k + 3];
        }
    }
    s += __shfl_xor_sync(0xffffffffu, s, 1);
    if (half == 0) {
        if (idx < N_ENT) g_hm[idx] = s;
        else g_ra[idx - N_ENT] = s;
    }
}

// single edge pass: flag-check + score + exp + denom + UNNORMALIZED aggregation.
// Warp cooperatively scatters each flagged edge (division deferred to gatherproj).
__global__ void k_edge(const int* __restrict__ ei, const int* __restrict__ et,
                       const float* __restrict__ Ew, const float* __restrict__ Rw) {
    int e = blockIdx.x * blockDim.x + threadIdx.x;
    int lane = threadIdx.x & 31;
    int f = 0, src = 0, ty = 0, p = 0;
    float ex = 0.f;
    bool pred = false;
    if (e < N_EDGE) {
        f = g_flag[ei[N_EDGE + e]];
        pred = (f != 0);
    }
    unsigned mask = __ballot_sync(0xffffffffu, pred);
    if (mask == 0) return;
    if (pred) {
        src = ei[e];
        ty = et[e];
        p = f - 1;
        float s = g_hdc[p] + g_hm[src] - g_ra[ty];
        s = (s >= 0.f) ? s : 0.2f * s;
        ex = expf(s);
        atomicAdd(&g_denomc[p], ex);
    }
    // warp-cooperative scatter of each flagged edge
    while (mask) {
        int bsel = __ffs(mask) - 1;
        mask &= mask - 1;
        int sb = __shfl_sync(0xffffffffu, src, bsel);
        int pb = __shfl_sync(0xffffffffu, p, bsel);
        int tb = __shfl_sync(0xffffffffu, ty, bsel);
        float eb = __shfl_sync(0xffffffffu, ex, bsel);
        if (lane < DE / 4) {
            float4 a = reinterpret_cast<const float4*>(&Ew[(size_t)sb * DE])[lane];
            float4 bb = reinterpret_cast<const float4*>(&Rw[(size_t)tb * DE])[lane];
            float4 v;
            v.x = eb * (a.x - bb.x); v.y = eb * (a.y - bb.y);
            v.z = eb * (a.z - bb.z); v.w = eb * (a.w - bb.w);
            float* pp = &g_Cagg[pb * DE + lane * 4];
            asm volatile("red.global.add.v4.f32 [%0], {%1,%2,%3,%4};"
                         :: "l"(pp), "f"(v.x), "f"(v.y), "f"(v.z), "f"(v.w) : "memory");
        }
    }
}

// gather Cagg rows (normalize by denom here), project through Wf, elu, bn1 stats
__global__ void k_gatherproj(const int* __restrict__ xb, const float* __restrict__ Wf,
                             const float* __restrict__ b1g, const float* __restrict__ b1b) {
    int b0 = blockIdx.x * 16;
    int t = threadIdx.x;
    __shared__ float C[16][DE];
    __shared__ int posr[16];
    __shared__ float invd[16];
    __shared__ float r1[128], r2[128];
    if (t < 16) {
        int pp = g_flag[xb[b0 + t]] - 1;
        posr[t] = pp;
        invd[t] = 1.f / (g_denomc[pp] + 1e-16f);
    }
    __syncthreads();
    for (int i = t; i < 16 * DE; i += 128) {
        int r = i / DE, k = i % DE;
        C[r][k] = g_Cagg[posr[r] * DE + k] * invd[r];
    }
    __syncthreads();
    int jl = t & 31, ng = t >> 5;
    float acc[4][4];
#pragma unroll
    for (int a = 0; a < 4; a++)
#pragma unroll
        for (int b = 0; b < 4; b++) acc[a][b] = 0.f;
    for (int k = 0; k < DE; k++) {
        float w0 = Wf[k * NOUT + jl];
        float w1 = Wf[k * NOUT + jl + 32];
        float w2 = Wf[k * NOUT + jl + 64];
        float w3 = Wf[k * NOUT + jl + 96];
#pragma unroll
        for (int nn = 0; nn < 4; nn++) {
            float e = C[ng * 4 + nn][k];
            acc[nn][0] += e * w0;
            acc[nn][1] += e * w1;
            acc[nn][2] += e * w2;
            acc[nn][3] += e * w3;
        }
    }
    float s = 0.f, ss = 0.f;
#pragma unroll
    for (int nn = 0; nn < 4; nn++)
#pragma unroll
        for (int q = 0; q < 4; q++) {
            float v = acc[nn][q];
            float e = (v > 0.f) ? v : expm1f(v);
            g_e[(b0 + ng * 4 + nn) * NOUT + q * 32 + jl] = e;
            s += e; ss += e * e;
        }
    r1[t] = s; r2[t] = ss;
    __syncthreads();
    for (int o = 64; o > 0; o >>= 1) {
        if (t < o) { r1[t] += r1[t + o]; r2[t] += r2[t + o]; }
        __syncthreads();
    }
    if (t == 0) { atomicAdd(&g_bn1[0], r1[0]); atomicAdd(&g_bn1[1], r2[0]); }
    __threadfence();
    __shared__ int lastf;
    if (t == 0) lastf = (atomicAdd(&g_c1, 1u) == gridDim.x - 1) ? 1 : 0;
    __syncthreads();
    if (lastf && t == 0) {
        float cnt = (float)(BATCH * NOUT);
        float mean = g_bn1[0] / cnt;
        float var = g_bn1[1] / cnt - mean * mean;
        float inv = rsqrtf(var + EPS);
        float sc = b1g[0] * inv;
        g_bn1[2] = sc;
        g_bn1[3] = b1b[0] - sc * mean;
    }
}

// conv (bn1 folded into input) + conv_b ; bn3 stats (+ last-block finalize)
__global__ void k_conv(const float* __restrict__ cw, const float* __restrict__ cb,
                       const float* __restrict__ b3g, const float* __restrict__ b3b) {
    int b = blockIdx.x, tid = threadIdx.x;
    __shared__ float es[NOUT];
    __shared__ float wsm[NUM_FILT * 9];
    __shared__ float co[NUM_FILT * CONV_W];
    float sc = g_bn1[2], sh = g_bn1[3];
    if (tid < NOUT) es[tid] = sc * g_e[b * NOUT + tid] + sh;
    for (int i = tid; i < NUM_FILT * 9; i += blockDim.x) wsm[i] = cw[i];
    __syncthreads();
    for (int i = tid; i < NUM_FILT * CONV_W; i += blockDim.x) {
        int c = i / CONV_W, w = i % CONV_W;
        float acc = cb[c];
#pragma unroll
        for (int k = 0; k < 9; k++) acc += wsm[c * 9 + k] * es[2 * w + k];
        co[i] = acc;
        g_conv[b * NUM_FILT * CONV_W + i] = acc;
    }
    __syncthreads();
    if (tid < NUM_FILT) {
        float s = 0.f, ss = 0.f;
        for (int w = 0; w < CONV_W; w++) {
            float v = co[tid * CONV_W + w];
            s += v; ss += v * v;
        }
        atomicAdd(&g_bn3sum[tid], s);
        atomicAdd(&g_bn3ss[tid], ss);
    }
    __threadfence();
    __shared__ int lastf;
    if (tid == 0) lastf = (atomicAdd(&g_c3, 1u) == gridDim.x - 1) ? 1 : 0;
    __syncthreads();
    if (lastf && tid < NUM_FILT) {
        float cnt = (float)(BATCH * CONV_W);
        float mean = g_bn3sum[tid] / cnt;
        float var = g_bn3ss[tid] / cnt - mean * mean;
        float inv = rsqrtf(var + EPS);
        float scc = b3g[tid] * inv;
        g_bn3sc[tid] = scc;
        g_bn3sh[tid] = b3b[tid] - scc * mean;
    }
}

// ---------------- tf32 GEMM 1: fc (split-K, atomics into g_y) ----------------
__global__ void __launch_bounds__(256) k_fc() {
    extern __shared__ unsigned sm[];
    unsigned* As = sm;                       // [2][128*SAP]
    unsigned* Bs = sm + 2 * 128 * SAP;       // [2][256*SAP]
    int t = threadIdx.x;
    int warp = t >> 5, lane = t & 31;
    int wm = warp >> 2, wn = warp & 3;
    int g = lane >> 2, tg = lane & 3;
    int m0 = blockIdx.x * 128;
    int kbase = blockIdx.y * 256;
    int nch = (blockIdx.y < 3) ? 8 : 6;      // 960 = 256*3 + 192

    for (int i = t; i < (256 - DT) * SAP; i += 256) {
        int r = DT + i / SAP, c = i % SAP;
        Bs[r * SAP + c] = 0u;
        Bs[256 * SAP + r * SAP + c] = 0u;
    }
    __syncthreads();

    float c[4][8][4];
#pragma unroll
    for (int i = 0; i < 4; i++)
#pragma unroll
        for (int j = 0; j < 8; j++)
#pragma unroll
            for (int q = 0; q < 4; q++) c[i][j][q] = 0.f;

    int arow = t >> 1, ahalf = (t & 1) * 16;
    const float* crow = g_conv + (size_t)(m0 + arow) * (NUM_FILT * CONV_W);

    auto stage = [&](int kt, int buf) {
        int k0g = kbase + kt * 32;
        unsigned* d = As + buf * 128 * SAP + arow * SAP + ahalf;
#pragma unroll
        for (int q = 0; q < 16; q++) {
            int kk = k0g + ahalf + q;
            int ch = kk / POOL_W, w = kk - ch * POOL_W;
            float sc = g_bn3sc[ch], sh = g_bn3sh[ch];
            float x0 = crow[ch * CONV_W + 2 * w];
            float x1 = crow[ch * CONV_W + 2 * w + 1];
            d[q] = f2tf(fmaxf(fmaxf(sc * x0 + sh, sc * x1 + sh), 0.f));
        }
        if (t < DT) {
            const float* src = g_fcwc + (size_t)t * FC_LEN + k0g;
            unsigned db = (unsigned)__cvta_generic_to_shared(Bs + buf * 256 * SAP + t * SAP);
#pragma unroll
            for (int q = 0; q < 8; q++) cp16(db + q * 16, src + q * 4);
        }
    };

    stage(0, 0);
    cp_commit();
    for (int kt = 0; kt < nch; kt++) {
        if (kt + 1 < nch) stage(kt + 1, (kt + 1) & 1);
        cp_commit();
        cp_wait1();
        __syncthreads();
        gemm_compute(As + (kt & 1) * 128 * SAP, Bs + (kt & 1) * 256 * SAP, c, wm, wn, g, tg);
        __syncthreads();
    }

#pragma unroll
    for (int mt = 0; mt < 4; mt++) {
        int mr = m0 + wm * 64 + mt * 16 + g;
#pragma unroll
        for (int nt = 0; nt < 8; nt++) {
            int n = wn * 64 + nt * 8 + 2 * tg;
            if (n < DT) {
                atomicAdd(&g_y[mr * DT + n], c[mt][nt][0]);
                atomicAdd(&g_y[mr * DT + n + 1], c[mt][nt][1]);
                atomicAdd(&g_y[(mr + 8) * DT + n], c[mt][nt][2]);
                atomicAdd(&g_y[(mr + 8) * DT + n + 1], c[mt][nt][3]);
            }
        }
    }
}

// y += bias (in place), bn2 stats, last-block finalize sc/sh
__global__ void k_ystat(const float* __restrict__ fcb, const float* __restrict__ b2g,
                        const float* __restrict__ b2b) {
    int r0 = blockIdx.x * 16, t = threadIdx.x;
    if (t < DT) {
        float bias = fcb[t];
        float s = 0.f, ss = 0.f;
#pragma unroll
        for (int i = 0; i < 16; i++) {
            float v = g_y[(r0 + i) * DT + t] + bias;
            g_y[(r0 + i) * DT + t] = v;
            s += v; ss += v * v;
        }
        atomicAdd(&g_bn2sum[t], s);
        atomicAdd(&g_bn2ss[t], ss);
    }
    __threadfence();
    __shared__ int lastf;
    if (t == 0) lastf = (atomicAdd(&g_c2, 1u) == gridDim.x - 1) ? 1 : 0;
    __syncthreads();
    if (lastf && t < DT) {
        float cnt = (float)BATCH;
        float mean = g_bn2sum[t] / cnt;
        float var = g_bn2ss[t] / cnt - mean * mean;
        float inv = rsqrtf(var + EPS);
        float sc = b2g[t] * inv;
        g_bn2sc[t] = sc;
        g_bn2sh[t] = b2b[t] - sc * mean;
    }
}

// z = relu(bn2(y)), tf32-rounded, K-padded
__global__ void k_apply() {
    int i = blockIdx.x * blockDim.x + threadIdx.x;
    if (i >= BATCH * DTP) return;
    int row = i / DTP, k = i - row * DTP;
    float v = 0.f;
    if (k < DT) {
        v = fmaxf(g_bn2sc[k] * g_y[row * DT + k] + g_bn2sh[k], 0.f);
        v = __uint_as_float(f2tf(v));
    }
    g_z[i] = v;
}

// ---------------- tf32 GEMM 2: out = sigmoid(Z @ Tw^T + bias) ----------------
__global__ void __launch_bounds__(256) k_out(const float* __restrict__ bbias,
                                             float* __restrict__ out) {
    extern __shared__ unsigned sm[];
    unsigned* As = sm;
    unsigned* Bs = sm + 2 * 128 * SAP;
    int t = threadIdx.x;
    int warp = t >> 5, lane = t & 31;
    int wm = warp >> 2, wn = warp & 3;
    int g = lane >> 2, tg = lane & 3;
    int m0 = blockIdx.x * 128;
    int n0 = blockIdx.y * 256;

    int inv0 = N_TYPE - n0;
    if (inv0 < 256) {
        for (int i = t; i < (256 - inv0) * SAP; i += 256) {
            int r = inv0 + i / SAP, c = i % SAP;
            Bs[r * SAP + c] = 0u;
            Bs[256 * SAP + r * SAP + c] = 0u;
        }
    }
    __syncthreads();

    float c[4][8][4];
#pragma unroll
    for (int i = 0; i < 4; i++)
#pragma unroll
        for (int j = 0; j < 8; j++)
#pragma unroll
            for (int q = 0; q < 4; q++) c[i][j][q] = 0.f;

    int arow = t >> 1, ahalf = (t & 1) * 16;
    const float* asrc0 = g_z + (size_t)(m0 + arow) * DTP + ahalf;
    unsigned da0 = (unsigned)__cvta_generic_to_shared(As + arow * SAP + ahalf);
    bool bvalid = (n0 + t < N_TYPE);
    const float* bsrc0 = g_twc + (size_t)(n0 + t) * DTP;
    unsigned db0 = (unsigned)__cvta_generic_to_shared(Bs + t * SAP);

    auto stage = [&](int kt, int buf) {
        int k0g = kt * 32;
        unsigned da = da0 + buf * 128 * SAP * 4;
        const float* sa = asrc0 + k0g;
#pragma unroll
        for (int q = 0; q < 4; q++) cp16(da + q * 16, sa + q * 4);
        if (bvalid) {
            unsigned db = db0 + buf * 256 * SAP * 4;
            const float* sb = bsrc0 + k0g;
#pragma unroll
            for (int q = 0; q < 8; q++) cp16(db + q * 16, sb + q * 4);
        }
    };

    const int NK = DTP / 32;
    stage(0, 0);
    cp_commit();
    for (int kt = 0; kt < NK; kt++) {
        if (kt + 1 < NK) stage(kt + 1, (kt + 1) & 1);
        cp_commit();
        cp_wait1();
        __syncthreads();
        gemm_compute(As + (kt & 1) * 128 * SAP, Bs + (kt & 1) * 256 * SAP, c, wm, wn, g, tg);
        __syncthreads();
    }

#pragma unroll
    for (int mt = 0; mt < 4; mt++) {
        int mr = m0 + wm * 64 + mt * 16 + g;
#pragma unroll
        for (int nt = 0; nt < 8; nt++) {
            int n = n0 + wn * 64 + nt * 8 + 2 * tg;
            if (n < N_TYPE) {
                float b0 = bbias[n], b1 = bbias[n + 1];
                float2 o0, o1;
                o0.x = 1.f / (1.f + expf(-(c[mt][nt][0] + b0)));
                o0.y = 1.f / (1.f + expf(-(c[mt][nt][1] + b1)));
                o1.x = 1.f / (1.f + expf(-(c[mt][nt][2] + b0)));
                o1.y = 1.f / (1.f + expf(-(c[mt][nt][3] + b1)));
                *reinterpret_cast<float2*>(&out[(size_t)mr * N_TYPE + n]) = o0;
                *reinterpret_cast<float2*>(&out[(size_t)(mr + 8) * N_TYPE + n]) = o1;
            }
        }
    }
}

// ---------------- launch ----------------
extern "C" void kernel_launch(void* const* d_in, const int* in_sizes, int n_in,
                              void* d_out, int out_size) {
    const int* xb = (const int*)d_in[0];
    const int* ei = (const int*)d_in[1];
    const int* et = (const int*)d_in[2];
    const float* Ew = (const float*)d_in[3];
    const float* Rw = (const float*)d_in[4];
    const float* Tw = (const float*)d_in[5];
    const float* Wf = (const float*)d_in[6];
    const float* av = (const float*)d_in[7];
    const float* cw = (const float*)d_in[8];
    const float* cb = (const float*)d_in[9];
    const float* b1g = (const float*)d_in[10];
    const float* b1b = (const float*)d_in[11];
    const float* b3g = (const float*)d_in[12];
    const float* b3b = (const float*)d_in[13];
    const float* b2g = (const float*)d_in[14];
    const float* b2b = (const float*)d_in[15];
    const float* fcw = (const float*)d_in[16];
    const float* fcb = (const float*)d_in[17];
    const float* bbias = (const float*)d_in[18];
    float* out = (float*)d_out;

    cudaFuncSetAttribute(k_fc, cudaFuncAttributeMaxDynamicSharedMemorySize, OUT_SMEM);
    cudaFuncSetAttribute(k_out, cudaFuncAttributeMaxDynamicSharedMemorySize, OUT_SMEM);

    k_prepinit<<<(P1 + P2 + P3 + 255) / 256, 256>>>(Wf, av, fcw, Tw);
    k_flag<<<BATCH, 160>>>(xb, Ew);
    k_hmra<<<((N_ENT + N_REL) * 2 + 255) / 256, 256>>>(Ew, Rw);
    k_edge<<<(N_EDGE + 255) / 256, 256>>>(ei, et, Ew, Rw);
    k_gatherproj<<<BATCH / 16, 128>>>(xb, Wf, b1g, b1b);
    k_conv<<<BATCH, 256>>>(cw, cb, b3g, b3b);
    {
        dim3 gg(BATCH / 128, 4);   // split-K = 4
        k_fc<<<gg, 256, OUT_SMEM>>>();
    }
    k_ystat<<<BATCH / 16, 256>>>(fcb, b2g, b2b);
    k_apply<<<(BATCH * DTP + 255) / 256, 256>>>();
    {
        dim3 gg(BATCH / 128, (N_TYPE + 255) / 256);
        k_out<<<gg, 256, OUT_SMEM>>>(bbias, out);
    }
}

// round 17
// speedup vs baseline: 1.4342x; 1.2618x over previous
#include <cuda_runtime.h>
#include <cuda_fp16.h>
#include <math.h>

#define N_ENT 50000
#define N_REL 237
#define N_TYPE 4000
#define DE 100
#define NOUT 128
#define DT 200
#define DTP 224
#define N_EDGE 800000
#define BATCH 4096
#define NUM_FILT 32
#define CONV_W 60
#define POOL_W 30
#define FC_LEN 960
#define EPS 1e-5f

// fp16 GEMM geometry: smem pitch 40 fp16 (20 uints) per 32-K row (conflict-free).
#define SAPH 40
#define UPITCH 20
#define OUT_SMEM (2 * (128 + 256) * SAPH * 2)   // 61440 B
#define FC_SMEM (2 * (64 + 256) * SAPH * 2)     // 51200 B

// ---------------- scratch ----------------
__device__ float g_hm[N_ENT];
__device__ float g_wa1[DE];
__device__ float g_wa2[DE];
__device__ float g_ra[N_REL];
__device__ int   g_flag[N_ENT];
__device__ float g_hdc[BATCH];
__device__ float g_denomc[BATCH];
__device__ float g_Cagg[BATCH * DE];
__device__ float g_e[BATCH * NOUT];
__device__ float g_conv[BATCH * NUM_FILT * CONV_W];
__device__ float g_y[BATCH * DT];
__device__ __half g_zh[BATCH * DTP];
__device__ __half g_twh[N_TYPE * DTP];
__device__ __half g_fcwh[DT * FC_LEN];
__device__ float g_bn1[4];
__device__ float g_bn3sum[NUM_FILT], g_bn3ss[NUM_FILT];
__device__ float g_bn3sc[NUM_FILT], g_bn3sh[NUM_FILT];
__device__ float g_bn2sum[DT], g_bn2ss[DT];
__device__ float g_bn2sc[DT], g_bn2sh[DT];
__device__ unsigned g_c1, g_c2, g_c3;

// ---------------- helpers ----------------
__device__ __forceinline__ void mma_f16(float c[4], const unsigned a[4], const unsigned b[2]) {
    asm volatile(
        "mma.sync.aligned.m16n8k16.row.col.f32.f16.f16.f32 "
        "{%0,%1,%2,%3}, {%4,%5,%6,%7}, {%8,%9}, {%0,%1,%2,%3};"
        : "+f"(c[0]), "+f"(c[1]), "+f"(c[2]), "+f"(c[3])
        : "r"(a[0]), "r"(a[1]), "r"(a[2]), "r"(a[3]), "r"(b[0]), "r"(b[1]));
}

__device__ __forceinline__ void cp16(unsigned dst, const void* src) {
    asm volatile("cp.async.ca.shared.global [%0], [%1], 16;" :: "r"(dst), "l"(src));
}
__device__ __forceinline__ void cp_commit() { asm volatile("cp.async.commit_group;"); }
__device__ __forceinline__ void cp_wait1() { asm volatile("cp.async.wait_group 1;" ::: "memory"); }

// 64x64 warp tile, one K=32 chunk (two m16n8k16 steps). A/B: uint views, UPITCH/row.
__device__ __forceinline__ void gemm_f16(const unsigned* __restrict__ A,
                                         const unsigned* __restrict__ B,
                                         float c[4][8][4], int wm, int wn,
                                         int g, int tg) {
#pragma unroll
    for (int ks = 0; ks < 2; ks++) {
        int kh = ks * 8;
        unsigned ar[4][4];
#pragma unroll
        for (int mt = 0; mt < 4; mt++) {
            int rb = (wm * 64 + mt * 16 + g) * UPITCH + kh + tg;
            ar[mt][0] = A[rb];
            ar[mt][1] = A[rb + 8 * UPITCH];
            ar[mt][2] = A[rb + 4];
            ar[mt][3] = A[rb + 8 * UPITCH + 4];
        }
#pragma unroll
        for (int nt = 0; nt < 8; nt++) {
            int nb = (wn * 64 + nt * 8 + g) * UPITCH + kh + tg;
            unsigned br[2] = {B[nb], B[nb + 4]};
#pragma unroll
            for (int mt = 0; mt < 4; mt++) mma_f16(c[mt][nt], ar[mt], br);
        }
    }
}

// 32x64 warp tile (k_fc: block M=64, warps 2x4)
__device__ __forceinline__ void gemm_f16_fc(const unsigned* __restrict__ A,
                                            const unsigned* __restrict__ B,
                                            float c[2][8][4], int wm, int wn,
                                            int g, int tg) {
#pragma unroll
    for (int ks = 0; ks < 2; ks++) {
        int kh = ks * 8;
        unsigned ar[2][4];
#pragma unroll
        for (int mt = 0; mt < 2; mt++) {
            int rb = (wm * 32 + mt * 16 + g) * UPITCH + kh + tg;
            ar[mt][0] = A[rb];
            ar[mt][1] = A[rb + 8 * UPITCH];
            ar[mt][2] = A[rb + 4];
            ar[mt][3] = A[rb + 8 * UPITCH + 4];
        }
#pragma unroll
        for (int nt = 0; nt < 8; nt++) {
            int nb = (wn * 64 + nt * 8 + g) * UPITCH + kh + tg;
            unsigned br[2] = {B[nb], B[nb + 4]};
#pragma unroll
            for (int mt = 0; mt < 2; mt++) mma_f16(c[mt][nt], ar[mt], br);
        }
    }
}

// ---------------- fused prep + init ----------------
#define P1 (DT * FC_LEN)
#define P2 (N_TYPE * DTP)
#define P3 (BATCH * DT)
__global__ void k_prepinit(const float* __restrict__ Wf, const float* __restrict__ av,
                           const float* __restrict__ fcw, const float* __restrict__ Tw) {
    int b = blockIdx.x, t = threadIdx.x;
    if (b < 13) {
        int k = b * 8 + (t >> 5);
        int lane = t & 31;
        if (k < DE) {
            float s1 = 0.f, s2 = 0.f;
#pragma unroll
            for (int q = 0; q < 4; q++) {
                int j = lane + q * 32;
                float w = Wf[k * NOUT + j];
                s1 += w * av[j];
                s2 += w * av[NOUT + j];
            }
#pragma unroll
            for (int o = 16; o > 0; o >>= 1) {
                s1 += __shfl_xor_sync(0xffffffffu, s1, o);
                s2 += __shfl_xor_sync(0xffffffffu, s2, o);
            }
            if (lane == 0) { g_wa1[k] = s1; g_wa2[k] = s2; }
        }
    }
    int i = b * blockDim.x + t;
    if (i < P1) {
        g_fcwh[i] = __float2half_rn(fcw[i]);
    } else if (i < P1 + P2) {
        int j = i - P1;
        int n = j / DTP, k = j % DTP;
        float v = (k < DT) ? Tw[n * DT + k] : 0.f;
        g_twh[j] = __float2half_rn(v);
    } else if (i < P1 + P2 + P3) {
        g_y[i - P1 - P2] = 0.f;
    }
    if (i < N_ENT) g_flag[i] = 0;
    if (i == 0) { g_c1 = 0u; g_c2 = 0u; g_c3 = 0u; }
    if (i < 2) g_bn1[i] = 0.f;
    if (i < NUM_FILT) { g_bn3sum[i] = 0.f; g_bn3ss[i] = 0.f; }
    if (i < DT) { g_bn2sum[i] = 0.f; g_bn2ss[i] = 0.f; }
}

// flag dst nodes, zero Cagg row + denom, compute hd
__global__ void k_flag(const int* __restrict__ xb, const float* __restrict__ Ew) {
    int b = blockIdx.x, t = threadIdx.x;
    int n = xb[b];
    if (t == 0) g_flag[n] = b + 1;
    if (t >= 32 && t - 32 < DE) g_Cagg[b * DE + (t - 32)] = 0.f;
    if (t == 32 + DE) g_denomc[b] = 0.f;
    if (t < 32) {
        float s = 0.f;
        for (int k = t; k < DE; k += 32) s += Ew[n * DE + k] * g_wa1[k];
#pragma unroll
        for (int o = 16; o > 0; o >>= 1) s += __shfl_xor_sync(0xffffffffu, s, o);
        if (t == 0) g_hdc[b] = s;
    }
}

// hm / ra: 2 threads per row
__global__ void k_hmra(const float* __restrict__ Ew, const float* __restrict__ Rw) {
    __shared__ float wa[DE];
    int t = threadIdx.x;
    if (t < DE) wa[t] = g_wa2[t];
    __syncthreads();
    int gid = blockIdx.x * 256 + t;
    int idx = gid >> 1, half = gid & 1;
    if (idx >= N_ENT + N_REL) return;
    const float* row = (idx < N_ENT) ? Ew + (size_t)idx * DE
                                     : Rw + (size_t)(idx - N_ENT) * DE;
    const float4* r4 = reinterpret_cast<const float4*>(row);
    int base = half ? 13 : 0;
    int cnt = half ? 12 : 13;
    float s = 0.f;
#pragma unroll
    for (int q = 0; q < 13; q++) {
        if (q < cnt) {
            float4 v = __ldg(r4 + base + q);
            int k = (base + q) * 4;
            s += v.x * wa[k] + v.y * wa[k + 1] + v.z * wa[k + 2] + v.w * wa[k + 3];
        }
    }
    s += __shfl_xor_sync(0xffffffffu, s, 1);
    if (half == 0) {
        if (idx < N_ENT) g_hm[idx] = s;
        else g_ra[idx - N_ENT] = s;
    }
}

// single edge pass: score + exp + denom + unnormalized aggregation
__global__ void k_edge(const int* __restrict__ ei, const int* __restrict__ et,
                       const float* __restrict__ Ew, const float* __restrict__ Rw) {
    int e = blockIdx.x * blockDim.x + threadIdx.x;
    int lane = threadIdx.x & 31;
    int f = 0, src = 0, ty = 0, p = 0;
    float ex = 0.f;
    bool pred = false;
    if (e < N_EDGE) {
        f = g_flag[ei[N_EDGE + e]];
        pred = (f != 0);
    }
    unsigned mask = __ballot_sync(0xffffffffu, pred);
    if (mask == 0) return;
    if (pred) {
        src = ei[e];
        ty = et[e];
        p = f - 1;
        float s = g_hdc[p] + g_hm[src] - g_ra[ty];
        s = (s >= 0.f) ? s : 0.2f * s;
        ex = expf(s);
        atomicAdd(&g_denomc[p], ex);
    }
    while (mask) {
        int bsel = __ffs(mask) - 1;
        mask &= mask - 1;
        int sb = __shfl_sync(0xffffffffu, src, bsel);
        int pb = __shfl_sync(0xffffffffu, p, bsel);
        int tb = __shfl_sync(0xffffffffu, ty, bsel);
        float eb = __shfl_sync(0xffffffffu, ex, bsel);
        if (lane < DE / 4) {
            float4 a = reinterpret_cast<const float4*>(&Ew[(size_t)sb * DE])[lane];
            float4 bb = reinterpret_cast<const float4*>(&Rw[(size_t)tb * DE])[lane];
            float4 v;
            v.x = eb * (a.x - bb.x); v.y = eb * (a.y - bb.y);
            v.z = eb * (a.z - bb.z); v.w = eb * (a.w - bb.w);
            float* pp = &g_Cagg[pb * DE + lane * 4];
            asm volatile("red.global.add.v4.f32 [%0], {%1,%2,%3,%4};"
                         :: "l"(pp), "f"(v.x), "f"(v.y), "f"(v.z), "f"(v.w) : "memory");
        }
    }
}

// gather Cagg (normalize), project through Wf, elu, bn1 stats
__global__ void k_gatherproj(const int* __restrict__ xb, const float* __restrict__ Wf,
                             const float* __restrict__ b1g, const float* __restrict__ b1b) {
    int b0 = blockIdx.x * 16;
    int t = threadIdx.x;
    __shared__ float C[16][DE];
    __shared__ int posr[16];
    __shared__ float invd[16];
    __shared__ float r1[128], r2[128];
    if (t < 16) {
        int pp = g_flag[xb[b0 + t]] - 1;
        posr[t] = pp;
        invd[t] = 1.f / (g_denomc[pp] + 1e-16f);
    }
    __syncthreads();
    for (int i = t; i < 16 * DE; i += 128) {
        int r = i / DE, k = i % DE;
        C[r][k] = g_Cagg[posr[r] * DE + k] * invd[r];
    }
    __syncthreads();
    int jl = t & 31, ng = t >> 5;
    float acc[4][4];
#pragma unroll
    for (int a = 0; a < 4; a++)
#pragma unroll
        for (int b = 0; b < 4; b++) acc[a][b] = 0.f;
    for (int k = 0; k < DE; k++) {
        float w0 = Wf[k * NOUT + jl];
        float w1 = Wf[k * NOUT + jl + 32];
        float w2 = Wf[k * NOUT + jl + 64];
        float w3 = Wf[k * NOUT + jl + 96];
#pragma unroll
        for (int nn = 0; nn < 4; nn++) {
            float e = C[ng * 4 + nn][k];
            acc[nn][0] += e * w0;
            acc[nn][1] += e * w1;
            acc[nn][2] += e * w2;
            acc[nn][3] += e * w3;
        }
    }
    float s = 0.f, ss = 0.f;
#pragma unroll
    for (int nn = 0; nn < 4; nn++)
#pragma unroll
        for (int q = 0; q < 4; q++) {
            float v = acc[nn][q];
            float e = (v > 0.f) ? v : expm1f(v);
            g_e[(b0 + ng * 4 + nn) * NOUT + q * 32 + jl] = e;
            s += e; ss += e * e;
        }
    r1[t] = s; r2[t] = ss;
    __syncthreads();
    for (int o = 64; o > 0; o >>= 1) {
        if (t < o) { r1[t] += r1[t + o]; r2[t] += r2[t + o]; }
        __syncthreads();
    }
    if (t == 0) { atomicAdd(&g_bn1[0], r1[0]); atomicAdd(&g_bn1[1], r2[0]); }
    __threadfence();
    __shared__ int lastf;
    if (t == 0) lastf = (atomicAdd(&g_c1, 1u) == gridDim.x - 1) ? 1 : 0;
    __syncthreads();
    if (lastf && t == 0) {
        float cnt = (float)(BATCH * NOUT);
        float mean = g_bn1[0] / cnt;
        float var = g_bn1[1] / cnt - mean * mean;
        float inv = rsqrtf(var + EPS);
        float sc = b1g[0] * inv;
        g_bn1[2] = sc;
        g_bn1[3] = b1b[0] - sc * mean;
    }
}

// conv + bn3 stats (+ last-block finalize)
__global__ void k_conv(const float* __restrict__ cw, const float* __restrict__ cb,
                       const float* __restrict__ b3g, const float* __restrict__ b3b) {
    int b = blockIdx.x, tid = threadIdx.x;
    __shared__ float es[NOUT];
    __shared__ float wsm[NUM_FILT * 9];
    __shared__ float co[NUM_FILT * CONV_W];
    float sc = g_bn1[2], sh = g_bn1[3];
    if (tid < NOUT) es[tid] = sc * g_e[b * NOUT + tid] + sh;
    for (int i = tid; i < NUM_FILT * 9; i += blockDim.x) wsm[i] = cw[i];
    __syncthreads();
    for (int i = tid; i < NUM_FILT * CONV_W; i += blockDim.x) {
        int c = i / CONV_W, w = i % CONV_W;
        float acc = cb[c];
#pragma unroll
        for (int k = 0; k < 9; k++) acc += wsm[c * 9 + k] * es[2 * w + k];
        co[i] = acc;
        g_conv[b * NUM_FILT * CONV_W + i] = acc;
    }
    __syncthreads();
    if (tid < NUM_FILT) {
        float s = 0.f, ss = 0.f;
        for (int w = 0; w < CONV_W; w++) {
            float v = co[tid * CONV_W + w];
            s += v; ss += v * v;
        }
        atomicAdd(&g_bn3sum[tid], s);
        atomicAdd(&g_bn3ss[tid], ss);
    }
    __threadfence();
    __shared__ int lastf;
    if (tid == 0) lastf = (atomicAdd(&g_c3, 1u) == gridDim.x - 1) ? 1 : 0;
    __syncthreads();
    if (lastf && tid < NUM_FILT) {
        float cnt = (float)(BATCH * CONV_W);
        float mean = g_bn3sum[tid] / cnt;
        float var = g_bn3ss[tid] / cnt - mean * mean;
        float inv = rsqrtf(var + EPS);
        float scc = b3g[tid] * inv;
        g_bn3sc[tid] = scc;
        g_bn3sh[tid] = b3b[tid] - scc * mean;
    }
}

// ---------------- fp16 GEMM 1: fc (block 64x256, split-K, atomics into g_y) ----------------
__global__ void __launch_bounds__(256) k_fc() {
    extern __shared__ unsigned sm[];
    unsigned* As = sm;                             // [2][64*UPITCH]
    unsigned* Bs = sm + 2 * 64 * UPITCH;           // [2][256*UPITCH]
    int t = threadIdx.x;
    int warp = t >> 5, lane = t & 31;
    int wm = warp >> 2, wn = warp & 3;             // 2x4 warps, warp tile 32x64
    int g = lane >> 2, tg = lane & 3;
    int m0 = blockIdx.x * 64;
    int kbase = blockIdx.y * 256;
    int nch = (blockIdx.y < 3) ? 8 : 6;            // 960 = 256*3 + 192

    for (int i = t; i < (256 - DT) * UPITCH; i += 256) {
        int r = DT + i / UPITCH, c = i % UPITCH;
        Bs[r * UPITCH + c] = 0u;
        Bs[256 * UPITCH + r * UPITCH + c] = 0u;
    }
    __syncthreads();

    float cc[2][8][4];
#pragma unroll
    for (int i = 0; i < 2; i++)
#pragma unroll
        for (int j = 0; j < 8; j++)
#pragma unroll
            for (int q = 0; q < 4; q++) cc[i][j][q] = 0.f;

    int arow = t >> 2, aq0 = (t & 3) * 8;          // 4 threads/row, 8 fp16 each
    const float* crow = g_conv + (size_t)(m0 + arow) * (NUM_FILT * CONV_W);

    auto stage = [&](int kt, int buf) {
        int k0g = kbase + kt * 32;
        // A: conv+bn3+relu+pool, packed half2 (4 uints per thread)
        unsigned* d = As + buf * 64 * UPITCH + arow * UPITCH + aq0 / 2;
#pragma unroll
        for (int q = 0; q < 4; q++) {
            int kk = k0g + aq0 + 2 * q;
            int ch0 = kk / POOL_W, w0i = kk - ch0 * POOL_W;
            int ch1 = (kk + 1) / POOL_W, w1i = (kk + 1) - ch1 * POOL_W;
            float sc0 = g_bn3sc[ch0], sh0 = g_bn3sh[ch0];
            float sc1 = g_bn3sc[ch1], sh1 = g_bn3sh[ch1];
            float v0 = fmaxf(fmaxf(sc0 * crow[ch0 * CONV_W + 2 * w0i] + sh0,
                                   sc0 * crow[ch0 * CONV_W + 2 * w0i + 1] + sh0), 0.f);
            float v1 = fmaxf(fmaxf(sc1 * crow[ch1 * CONV_W + 2 * w1i] + sh1,
                                   sc1 * crow[ch1 * CONV_W + 2 * w1i + 1] + sh1), 0.f);
            __half2 h = __floats2half2_rn(v0, v1);
            d[q] = *reinterpret_cast<unsigned*>(&h);
        }
        // B: fcw rows (fp16), 64B per row per chunk
        if (t < DT) {
            const __half* src = g_fcwh + (size_t)t * FC_LEN + k0g;
            unsigned db = (unsigned)__cvta_generic_to_shared(
                reinterpret_cast<__half*>(Bs) + buf * 256 * SAPH + t * SAPH);
#pragma unroll
            for (int q = 0; q < 4; q++) cp16(db + q * 16, src + q * 8);
        }
    };

    stage(0, 0);
    cp_commit();
    for (int kt = 0; kt < nch; kt++) {
        if (kt + 1 < nch) stage(kt + 1, (kt + 1) & 1);
        cp_commit();
        cp_wait1();
        __syncthreads();
        gemm_f16_fc(As + (kt & 1) * 64 * UPITCH, Bs + (kt & 1) * 256 * UPITCH,
                    cc, wm, wn, g, tg);
        __syncthreads();
    }

#pragma unroll
    for (int mt = 0; mt < 2; mt++) {
        int mr = m0 + wm * 32 + mt * 16 + g;
#pragma unroll
        for (int nt = 0; nt < 8; nt++) {
            int n = wn * 64 + nt * 8 + 2 * tg;
            if (n < DT) {
                atomicAdd(&g_y[mr * DT + n], cc[mt][nt][0]);
                atomicAdd(&g_y[mr * DT + n + 1], cc[mt][nt][1]);
                atomicAdd(&g_y[(mr + 8) * DT + n], cc[mt][nt][2]);
                atomicAdd(&g_y[(mr + 8) * DT + n + 1], cc[mt][nt][3]);
            }
        }
    }
}

// y += bias, bn2 stats, last-block finalize
__global__ void k_ystat(const float* __restrict__ fcb, const float* __restrict__ b2g,
                        const float* __restrict__ b2b) {
    int r0 = blockIdx.x * 16, t = threadIdx.x;
    if (t < DT) {
        float bias = fcb[t];
        float s = 0.f, ss = 0.f;
#pragma unroll
        for (int i = 0; i < 16; i++) {
            float v = g_y[(r0 + i) * DT + t] + bias;
            g_y[(r0 + i) * DT + t] = v;
            s += v; ss += v * v;
        }
        atomicAdd(&g_bn2sum[t], s);
        atomicAdd(&g_bn2ss[t], ss);
    }
    __threadfence();
    __shared__ int lastf;
    if (t == 0) lastf = (atomicAdd(&g_c2, 1u) == gridDim.x - 1) ? 1 : 0;
    __syncthreads();
    if (lastf && t < DT) {
        float cnt = (float)BATCH;
        float mean = g_bn2sum[t] / cnt;
        float var = g_bn2ss[t] / cnt - mean * mean;
        float inv = rsqrtf(var + EPS);
        float sc = b2g[t] * inv;
        g_bn2sc[t] = sc;
        g_bn2sh[t] = b2b[t] - sc * mean;
    }
}

// z = relu(bn2(y)) -> fp16, K-padded
__global__ void k_apply() {
    int i = blockIdx.x * blockDim.x + threadIdx.x;
    if (i >= BATCH * DTP) return;
    int row = i / DTP, k = i - row * DTP;
    float v = 0.f;
    if (k < DT) v = fmaxf(g_bn2sc[k] * g_y[row * DT + k] + g_bn2sh[k], 0.f);
    g_zh[i] = __float2half_rn(v);
}

// ---------------- fp16 GEMM 2: out = sigmoid(Z @ Tw^T + bias) ----------------
__global__ void __launch_bounds__(256) k_out(const float* __restrict__ bbias,
                                             float* __restrict__ out) {
    extern __shared__ unsigned sm[];
    unsigned* As = sm;                             // [2][128*UPITCH]
    unsigned* Bs = sm + 2 * 128 * UPITCH;          // [2][256*UPITCH]
    int t = threadIdx.x;
    int warp = t >> 5, lane = t & 31;
    int wm = warp >> 2, wn = warp & 3;
    int g = lane >> 2, tg = lane & 3;
    int m0 = blockIdx.x * 128;
    int n0 = blockIdx.y * 256;

    int inv0 = N_TYPE - n0;
    if (inv0 < 256) {
        for (int i = t; i < (256 - inv0) * UPITCH; i += 256) {
            int r = inv0 + i / UPITCH, c = i % UPITCH;
            Bs[r * UPITCH + c] = 0u;
            Bs[256 * UPITCH + r * UPITCH + c] = 0u;
        }
    }
    __syncthreads();

    float c[4][8][4];
#pragma unroll
    for (int i = 0; i < 4; i++)
#pragma unroll
        for (int j = 0; j < 8; j++)
#pragma unroll
            for (int q = 0; q < 4; q++) c[i][j][q] = 0.f;

    int arow = t >> 1, ahalf = (t & 1) * 16;
    const __half* asrc0 = g_zh + (size_t)(m0 + arow) * DTP + ahalf;
    unsigned da0 = (unsigned)__cvta_generic_to_shared(
        reinterpret_cast<__half*>(As) + arow * SAPH + ahalf);
    bool bvalid = (n0 + t < N_TYPE);
    const __half* bsrc0 = g_twh + (size_t)(n0 + t) * DTP;
    unsigned db0 = (unsigned)__cvta_generic_to_shared(
        reinterpret_cast<__half*>(Bs) + t * SAPH);

    auto stage = [&](int kt, int buf) {
        int k0g = kt * 32;
        unsigned da = da0 + buf * 128 * SAPH * 2;
        const __half* sa = asrc0 + k0g;
        cp16(da, sa);
        cp16(da + 16, sa + 8);
        if (bvalid) {
            unsigned db = db0 + buf * 256 * SAPH * 2;
            const __half* sb = bsrc0 + k0g;
#pragma unroll
            for (int q = 0; q < 4; q++) cp16(db + q * 16, sb + q * 8);
        }
    };

    const int NK = DTP / 32;   // 7
    stage(0, 0);
    cp_commit();
    for (int kt = 0; kt < NK; kt++) {
        if (kt + 1 < NK) stage(kt + 1, (kt + 1) & 1);
        cp_commit();
        cp_wait1();
        __syncthreads();
        gemm_f16(As + (kt & 1) * 128 * UPITCH, Bs + (kt & 1) * 256 * UPITCH,
                 c, wm, wn, g, tg);
        __syncthreads();
    }

#pragma unroll
    for (int mt = 0; mt < 4; mt++) {
        int mr = m0 + wm * 64 + mt * 16 + g;
#pragma unroll
        for (int nt = 0; nt < 8; nt++) {
            int n = n0 + wn * 64 + nt * 8 + 2 * tg;
            if (n < N_TYPE) {
                float b0 = bbias[n], b1 = bbias[n + 1];
                float2 o0, o1;
                o0.x = 1.f / (1.f + expf(-(c[mt][nt][0] + b0)));
                o0.y = 1.f / (1.f + expf(-(c[mt][nt][1] + b1)));
                o1.x = 1.f / (1.f + expf(-(c[mt][nt][2] + b0)));
                o1.y = 1.f / (1.f + expf(-(c[mt][nt][3] + b1)));
                *reinterpret_cast<float2*>(&out[(size_t)mr * N_TYPE + n]) = o0;
                *reinterpret_cast<float2*>(&out[(size_t)(mr + 8) * N_TYPE + n]) = o1;
            }
        }
    }
}

// ---------------- launch ----------------
extern "C" void kernel_launch(void* const* d_in, const int* in_sizes, int n_in,
                              void* d_out, int out_size) {
    const int* xb = (const int*)d_in[0];
    const int* ei = (const int*)d_in[1];
    const int* et = (const int*)d_in[2];
    const float* Ew = (const float*)d_in[3];
    const float* Rw = (const float*)d_in[4];
    const float* Tw = (const float*)d_in[5];
    const float* Wf = (const float*)d_in[6];
    const float* av = (const float*)d_in[7];
    const float* cw = (const float*)d_in[8];
    const float* cb = (const float*)d_in[9];
    const float* b1g = (const float*)d_in[10];
    const float* b1b = (const float*)d_in[11];
    const float* b3g = (const float*)d_in[12];
    const float* b3b = (const float*)d_in[13];
    const float* b2g = (const float*)d_in[14];
    const float* b2b = (const float*)d_in[15];
    const float* fcw = (const float*)d_in[16];
    const float* fcb = (const float*)d_in[17];
    const float* bbias = (const float*)d_in[18];
    float* out = (float*)d_out;

    cudaFuncSetAttribute(k_fc, cudaFuncAttributeMaxDynamicSharedMemorySize, FC_SMEM);
    cudaFuncSetAttribute(k_out, cudaFuncAttributeMaxDynamicSharedMemorySize, OUT_SMEM);

    k_prepinit<<<(P1 + P2 + P3 + 255) / 256, 256>>>(Wf, av, fcw, Tw);
    k_flag<<<BATCH, 160>>>(xb, Ew);
    k_hmra<<<((N_ENT + N_REL) * 2 + 255) / 256, 256>>>(Ew, Rw);
    k_edge<<<(N_EDGE + 255) / 256, 256>>>(ei, et, Ew, Rw);
    k_gatherproj<<<BATCH / 16, 128>>>(xb, Wf, b1g, b1b);
    k_conv<<<BATCH, 256>>>(cw, cb, b3g, b3b);
    {
        dim3 gg(BATCH / 64, 4);   // block M=64, split-K = 4
        k_fc<<<gg, 256, FC_SMEM>>>();
    }
    k_ystat<<<BATCH / 16, 256>>>(fcb, b2g, b2b);
    k_apply<<<(BATCH * DTP + 255) / 256, 256>>>();
    {
        dim3 gg(BATCH / 128, (N_TYPE + 255) / 256);
        k_out<<<gg, 256, OUT_SMEM>>>(bbias, out);
    }
}